// round 10
// baseline (speedup 1.0000x reference)
#include <cuda_runtime.h>
#include <cuda_bf16.h>

// BuzzLoss: B=8192 rows, T=1024 cols.
// cp.async (LDGSTS) staging: each 256-thread CTA stages 8 rows of conf+acc
// (64 KB) into smem with 16B cp.async ops -> 8 KB in flight per warp at ZERO
// register cost (the R7-R9 lesson: register-resident buffering caps MLP at
// ~2-4 loads no matter the reg budget). After wait+barrier, warp w runs the
// R8 per-row math (segment-local reduction -> 8 interleaved product-scans ->
// serial 8-combine) reading from smem. 3 CTAs/SM (64KB smem) = 192KB DRAM
// bytes in flight per SM.

#define FULL_MASK 0xFFFFFFFFu
#define ROWS_PER_CTA 8
#define SMEM_BYTES (2 * ROWS_PER_CTA * 1024 * 4)   // 65536

__global__ void buzz_zero_kernel(float* out) {
    out[0] = 0.0f;
}

__device__ __forceinline__ void cp_async16(void* smem_dst, const void* gmem_src) {
    unsigned saddr = (unsigned)__cvta_generic_to_shared(smem_dst);
    asm volatile("cp.async.cg.shared.global [%0], [%1], 16;\n"
                 :: "r"(saddr), "l"(gmem_src));
}

__global__ __launch_bounds__(256)
void buzz_loss_kernel(const float* __restrict__ conf,
                      const float* __restrict__ acc,
                      float* __restrict__ out,
                      float negInvB) {
    extern __shared__ float4 smem4[];            // [4096] float4 = 64KB
    float4* s_c = smem4;                         // 2048 float4 (8 rows conf)
    float4* s_a = smem4 + 2048;                  // 2048 float4 (8 rows acc)

    __shared__ float s_total;

    const int tid  = threadIdx.x;
    const int lane = tid & 31;
    const int wid  = tid >> 5;
    const size_t row0 = (size_t)blockIdx.x * ROWS_PER_CTA;

    if (tid == 0) s_total = 0.0f;

    const float4* c4 = reinterpret_cast<const float4*>(conf + row0 * 1024);
    const float4* a4 = reinterpret_cast<const float4*>(acc  + row0 * 1024);

    // ---- Stage 64KB via cp.async: 16 ops per thread, zero reg cost ----
    #pragma unroll
    for (int k = 0; k < 8; k++) {
        const int i = k * 256 + tid;             // 0..2047
        cp_async16(&s_c[i], &c4[i]);
    }
    #pragma unroll
    for (int k = 0; k < 8; k++) {
        const int i = k * 256 + tid;
        cp_async16(&s_a[i], &a4[i]);
    }
    asm volatile("cp.async.commit_group;\n" ::: "memory");
    asm volatile("cp.async.wait_all;\n" ::: "memory");
    __syncthreads();

    // ---- Per-row math: warp wid owns row wid ----
    const float4* rc = s_c + wid * 256;
    const float4* ra = s_a + wid * 256;

    float p[8], s1loc[8], s2loc[8];
    float lastA = 0.0f;

    #pragma unroll
    for (int j = 0; j < 8; j++) {
        const float4 c = rc[j * 32 + lane];
        const float4 a = ra[j * 32 + lane];

        const float q0 = 1.0f - c.x;
        const float q1 = 1.0f - c.y;
        const float q2 = 1.0f - c.z;
        const float q3 = 1.0f - c.w;

        const float lb0 = c.x;
        const float lb1 = c.y * q0;
        const float lb2 = c.z * (q0 * q1);
        const float lb3 = c.w * (q0 * q1 * q2);

        p[j] = (q0 * q1) * (q2 * q3);
        s1loc[j] = fmaf(lb0, a.x, fmaf(lb1, a.y, fmaf(lb2, a.z, lb3 * a.w)));
        s2loc[j] = (lb0 + lb1) + (lb2 + lb3);

        if (j == 7) lastA = a.w;                 // lane 31 -> acc[row, 1023]
    }

    // 8 interleaved warp inclusive product-scans
    #pragma unroll
    for (int d = 1; d < 32; d <<= 1) {
        #pragma unroll
        for (int j = 0; j < 8; j++) {
            float v = __shfl_up_sync(FULL_MASK, p[j], d);
            if (lane >= d) p[j] *= v;
        }
    }

    float tot[8], E[8];
    #pragma unroll
    for (int j = 0; j < 8; j++) {
        tot[j] = __shfl_sync(FULL_MASK, p[j], 31);
        E[j]   = __shfl_up_sync(FULL_MASK, p[j], 1);
        if (lane == 0) E[j] = 1.0f;
    }

    // Serial cross-segment chain (8 deep)
    float R = 1.0f, s1 = 0.0f, s2 = 0.0f;
    #pragma unroll
    for (int j = 0; j < 8; j++) {
        const float Ej = E[j] * R;
        s1 = fmaf(Ej, s1loc[j], s1);
        s2 = fmaf(Ej, s2loc[j], s2);
        R *= tot[j];
    }

    // Warp reduce
    #pragma unroll
    for (int d = 16; d >= 1; d >>= 1) {
        s1 += __shfl_down_sync(FULL_MASK, s1, d);
        s2 += __shfl_down_sync(FULL_MASK, s2, d);
    }
    const float accLast = __shfl_sync(FULL_MASK, lastA, 31);

    if (lane == 0) {
        const float score = s1 + (1.0f - s2) * accLast;
        atomicAdd(&s_total, score);
    }

    __syncthreads();
    if (tid == 0) {
        atomicAdd(out, s_total * negInvB);
    }
}

extern "C" void kernel_launch(void* const* d_in, const int* in_sizes, int n_in,
                              void* d_out, int out_size) {
    const float* conf = (const float*)d_in[0];
    const float* acc  = (const float*)d_in[1];
    float* out = (float*)d_out;

    const int total = in_sizes[0];
    const int T = 1024;
    const int B = total / T;

    cudaFuncSetAttribute(buzz_loss_kernel,
                         cudaFuncAttributeMaxDynamicSharedMemorySize,
                         SMEM_BYTES);

    buzz_zero_kernel<<<1, 1>>>(out);
    buzz_loss_kernel<<<B / ROWS_PER_CTA, 256, SMEM_BYTES>>>(conf, acc, out,
                                                            -1.0f / (float)B);
}

// round 11
// speedup vs baseline: 1.2875x; 1.2875x over previous
#include <cuda_runtime.h>
#include <cuda_bf16.h>

// BuzzLoss: B=8192 rows, T=1024 cols.
// ONE WARP PER ROW (R8 math), 4 rows per 128-thread CTA, grid 2048 for fine
// wave granularity. Single kernel: ticket-based last-CTA finalize with
// self-resetting __device__ globals (no zero-kernel graph node).
// Loads: 16 coalesced LDG.128 per warp, streaming (.cs), segment-reduced on
// arrival to (p, s1loc, s2loc); then 8 interleaved warp product-scans and an
// 8-deep serial combine. One global atomic per CTA.

#define FULL_MASK 0xFFFFFFFFu
#define ROWS_PER_CTA 4
#define THREADS 128

__device__ float g_partial = 0.0f;
__device__ unsigned int g_ticket = 0u;

__global__ __launch_bounds__(THREADS)
void buzz_loss_kernel(const float* __restrict__ conf,
                      const float* __restrict__ acc,
                      float* __restrict__ out,
                      float negInvB) {
    const int tid  = threadIdx.x;
    const int lane = tid & 31;
    const int wid  = tid >> 5;
    const size_t row = (size_t)blockIdx.x * ROWS_PER_CTA + wid;

    __shared__ float s_total;
    if (tid == 0) s_total = 0.0f;
    __syncthreads();

    const float4* c4 = reinterpret_cast<const float4*>(conf + row * 1024) + lane;
    const float4* a4 = reinterpret_cast<const float4*>(acc  + row * 1024) + lane;

    // ---- Phase 1: load (streaming) + immediate per-segment reduction ----
    float p[8], s1loc[8], s2loc[8];
    float lastA = 0.0f;

    #pragma unroll
    for (int j = 0; j < 8; j++) {
        const float4 c = __ldcs(&c4[j * 32]);
        const float4 a = __ldcs(&a4[j * 32]);

        const float q0 = 1.0f - c.x;
        const float q1 = 1.0f - c.y;
        const float q2 = 1.0f - c.z;
        const float q3 = 1.0f - c.w;

        const float lb0 = c.x;
        const float lb1 = c.y * q0;
        const float lb2 = c.z * (q0 * q1);
        const float lb3 = c.w * (q0 * q1 * q2);

        p[j] = (q0 * q1) * (q2 * q3);
        s1loc[j] = fmaf(lb0, a.x, fmaf(lb1, a.y, fmaf(lb2, a.z, lb3 * a.w)));
        s2loc[j] = (lb0 + lb1) + (lb2 + lb3);

        if (j == 7) lastA = a.w;            // lane 31 -> acc[row, 1023]
    }

    // ---- Phase 2: 8 interleaved warp inclusive product-scans ----
    #pragma unroll
    for (int d = 1; d < 32; d <<= 1) {
        #pragma unroll
        for (int j = 0; j < 8; j++) {
            float v = __shfl_up_sync(FULL_MASK, p[j], d);
            if (lane >= d) p[j] *= v;
        }
    }

    float tot[8], E[8];
    #pragma unroll
    for (int j = 0; j < 8; j++) {
        tot[j] = __shfl_sync(FULL_MASK, p[j], 31);
        E[j]   = __shfl_up_sync(FULL_MASK, p[j], 1);
        if (lane == 0) E[j] = 1.0f;
    }

    // Serial cross-segment chain (8 deep)
    float R = 1.0f, s1 = 0.0f, s2 = 0.0f;
    #pragma unroll
    for (int j = 0; j < 8; j++) {
        const float Ej = E[j] * R;
        s1 = fmaf(Ej, s1loc[j], s1);
        s2 = fmaf(Ej, s2loc[j], s2);
        R *= tot[j];
    }

    // Warp reduce
    #pragma unroll
    for (int d = 16; d >= 1; d >>= 1) {
        s1 += __shfl_down_sync(FULL_MASK, s1, d);
        s2 += __shfl_down_sync(FULL_MASK, s2, d);
    }
    const float accLast = __shfl_sync(FULL_MASK, lastA, 31);

    if (lane == 0) {
        const float score = s1 + (1.0f - s2) * accLast;
        atomicAdd(&s_total, score);
    }
    __syncthreads();

    // ---- Finalize: last CTA reduces and self-resets the globals ----
    if (tid == 0) {
        atomicAdd(&g_partial, s_total);
        __threadfence();
        const unsigned t = atomicAdd(&g_ticket, 1u);
        if (t == gridDim.x - 1) {
            const float total = atomicExch(&g_partial, 0.0f);
            atomicExch(&g_ticket, 0u);
            out[0] = total * negInvB;
        }
    }
}

extern "C" void kernel_launch(void* const* d_in, const int* in_sizes, int n_in,
                              void* d_out, int out_size) {
    const float* conf = (const float*)d_in[0];
    const float* acc  = (const float*)d_in[1];
    float* out = (float*)d_out;

    const int total = in_sizes[0];
    const int T = 1024;
    const int B = total / T;

    buzz_loss_kernel<<<B / ROWS_PER_CTA, THREADS>>>(conf, acc, out,
                                                    -1.0f / (float)B);
}